// round 6
// baseline (speedup 1.0000x reference)
#include <cuda_runtime.h>
#include <cuda_bf16.h>
#include <cstdint>

// ---------------- problem constants ----------------
#define BB   16
#define NN   3136
#define DD   512
#define HDim 64
#define MM   (BB * NN)        // 50176 rows
#define HH   56
#define SPLIT 14
#define TOKS  (NN / SPLIT)    // 224

// ---------------- scratch ----------------
__device__ __align__(256) float g_q[(size_t)MM * DD];
__device__ __align__(256) float g_k[(size_t)MM * DD];
__device__ __align__(256) float g_v[(size_t)MM * DD];
__device__ __align__(256) float g_y[(size_t)MM * DD];
__device__ __align__(256) float g_ctx_part[(size_t)SPLIT * 128 * 64 * 64];
__device__ __align__(256) float g_ksum_part[(size_t)SPLIT * 128 * 64];
__device__ __align__(256) float g_ctx[(size_t)128 * 64 * 64];
__device__ __align__(256) float g_ksum[(size_t)128 * 64];

__device__ __align__(256) __nv_bfloat16 g_xhi[(size_t)MM * DD];
__device__ __align__(256) __nv_bfloat16 g_xlo[(size_t)MM * DD];
__device__ __align__(256) __nv_bfloat16 g_yhi[(size_t)MM * DD];
__device__ __align__(256) __nv_bfloat16 g_ylo[(size_t)MM * DD];
// transposed weights [n][k]: rows 0-511=Wq, 512-1023=Wkv(k), 1024-1535=Wkv(v), then Wp
__device__ __align__(256) __nv_bfloat16 g_whi[4][(size_t)DD * DD];
__device__ __align__(256) __nv_bfloat16 g_wlo[4][(size_t)DD * DD];

// ---------------- helpers ----------------
__device__ __forceinline__ uint32_t smem_to_u32(const void* p) {
    uint32_t a;
    asm("{ .reg .u64 t; cvta.to.shared.u64 t, %1; cvt.u32.u64 %0, t; }" : "=r"(a) : "l"(p));
    return a;
}
#define SWZ(o) ((o) ^ (((o) >> 3) & 0x70))

#define CP16(dst, src) \
    asm volatile("cp.async.cg.shared.global [%0], [%1], 16;" :: "r"(dst), "l"(src) : "memory")
#define CP_COMMIT() asm volatile("cp.async.commit_group;" ::: "memory")
#define CP_WAIT(n)  asm volatile("cp.async.wait_group %0;" :: "n"(n) : "memory")

__device__ __forceinline__ void ldsm4(uint32_t addr, uint32_t* r) {
    asm volatile("ldmatrix.sync.aligned.m8n8.x4.shared.b16 {%0,%1,%2,%3}, [%4];"
                 : "=r"(r[0]), "=r"(r[1]), "=r"(r[2]), "=r"(r[3]) : "r"(addr));
}
__device__ __forceinline__ void mma16816(float* d, const uint32_t* a, const uint32_t* b) {
    asm volatile(
        "mma.sync.aligned.m16n8k16.row.col.f32.bf16.bf16.f32 "
        "{%0,%1,%2,%3}, {%4,%5,%6,%7}, {%8,%9}, {%0,%1,%2,%3};"
        : "+f"(d[0]), "+f"(d[1]), "+f"(d[2]), "+f"(d[3])
        : "r"(a[0]), "r"(a[1]), "r"(a[2]), "r"(a[3]), "r"(b[0]), "r"(b[1]));
}

// ---------------- input split kernels ----------------
__global__ __launch_bounds__(256)
void split_x_kernel(const float* __restrict__ x)
{
    size_t i = (size_t)blockIdx.x * 256 + threadIdx.x;   // over MM*DD/4
    float4 v = ((const float4*)x)[i];
    __nv_bfloat16 h0 = __float2bfloat16(v.x), h1 = __float2bfloat16(v.y);
    __nv_bfloat16 h2 = __float2bfloat16(v.z), h3 = __float2bfloat16(v.w);
    __nv_bfloat16 l0 = __float2bfloat16(v.x - __bfloat162float(h0));
    __nv_bfloat16 l1 = __float2bfloat16(v.y - __bfloat162float(h1));
    __nv_bfloat16 l2 = __float2bfloat16(v.z - __bfloat162float(h2));
    __nv_bfloat16 l3 = __float2bfloat16(v.w - __bfloat162float(h3));
    __nv_bfloat162* ph = (__nv_bfloat162*)g_xhi;
    __nv_bfloat162* pl = (__nv_bfloat162*)g_xlo;
    ph[2 * i + 0] = __nv_bfloat162(h0, h1);
    ph[2 * i + 1] = __nv_bfloat162(h2, h3);
    pl[2 * i + 0] = __nv_bfloat162(l0, l1);
    pl[2 * i + 1] = __nv_bfloat162(l2, l3);
}

__global__ __launch_bounds__(256)
void prep_w_kernel(const float* __restrict__ Wq, const float* __restrict__ Wkv,
                   const float* __restrict__ Wp)
{
    int idx = blockIdx.x * 256 + threadIdx.x;   // 0..DD*DD-1, output [n][k]
    int n = idx / DD, k = idx % DD;
    float v0 = Wq[(size_t)k * DD + n];
    float v1 = Wkv[(size_t)k * 2 * DD + n];
    float v2 = Wkv[(size_t)k * 2 * DD + DD + n];
    float v3 = Wp[(size_t)k * DD + n];
#pragma unroll
    for (int m = 0; m < 4; m++) {
        float v = (m == 0) ? v0 : (m == 1) ? v1 : (m == 2) ? v2 : v3;
        __nv_bfloat16 h = __float2bfloat16(v);
        g_whi[m][idx] = h;
        g_wlo[m][idx] = __float2bfloat16(v - __bfloat162float(h));
    }
}

// ---------------- HMMA GEMM core ----------------
// smem per stage: Ahi,Alo,Bhi,Blo each 128x64 bf16 (16KB) = 64KB; 2 stages = 128KB
#define ST_AHI 0
#define ST_ALO 16384
#define ST_BHI 32768
#define ST_BLO 49152
#define STAGE_BYTES 65536
#define GEMM_SMEM (2 * STAGE_BYTES)

__device__ __forceinline__ void gemm_load_chunk(
    char* smem, int stage, int c, int m0, int n0, int tid,
    const __nv_bfloat16* __restrict__ Ahi, const __nv_bfloat16* __restrict__ Alo,
    const __nv_bfloat16* __restrict__ Bhi, const __nv_bfloat16* __restrict__ Blo)
{
    const uint32_t sb = smem_to_u32(smem) + stage * STAGE_BYTES;
#pragma unroll
    for (int i = 0; i < 4; i++) {
        int u = tid + i * 256;          // 0..1023 16B units
        int row = u >> 3, col = u & 7;
        uint32_t off = SWZ((uint32_t)(row * 128 + col * 16));
        size_t ga = (size_t)(m0 + row) * DD + c * 64 + col * 8;
        size_t gb = (size_t)(n0 + row) * DD + c * 64 + col * 8;
        CP16(sb + ST_AHI + off, Ahi + ga);
        CP16(sb + ST_ALO + off, Alo + ga);
        CP16(sb + ST_BHI + off, Bhi + gb);
        CP16(sb + ST_BLO + off, Blo + gb);
    }
}

// Mainloop body shared by both GEMM kernels: one __syncthreads per k-iter,
// next chunk's cp.async issued after the barrier (slot last read one barrier ago).
__device__ __forceinline__ void gemm_mainloop(
    char* smem, int m0, int n0, int tid, int wm, int wn, int lane,
    const __nv_bfloat16* Ahi, const __nv_bfloat16* Alo,
    const __nv_bfloat16* Bhi, const __nv_bfloat16* Blo,
    float acc[4][4][4])
{
    gemm_load_chunk(smem, 0, 0, m0, n0, tid, Ahi, Alo, Bhi, Blo);
    CP_COMMIT();
    const uint32_t sbase = smem_to_u32(smem);

    for (int c = 0; c < 8; c++) {
        CP_WAIT(0);
        __syncthreads();
        if (c < 7) {
            gemm_load_chunk(smem, (c + 1) & 1, c + 1, m0, n0, tid, Ahi, Alo, Bhi, Blo);
            CP_COMMIT();
        }
        const uint32_t st = sbase + (c & 1) * STAGE_BYTES;
#pragma unroll
        for (int kk = 0; kk < 4; kk++) {
            uint32_t ah[4][4], al[4][4], bh[2][4], bl[2][4];
#pragma unroll
            for (int mi = 0; mi < 4; mi++) {
                int row = wm * 64 + mi * 16 + (lane & 15);
                uint32_t off = SWZ((uint32_t)(row * 128 + kk * 32 + (lane >> 4) * 16));
                ldsm4(st + ST_AHI + off, ah[mi]);
                ldsm4(st + ST_ALO + off, al[mi]);
            }
#pragma unroll
            for (int g = 0; g < 2; g++) {
                int n = wn * 32 + g * 16 + (lane & 7) + ((lane & 16) ? 8 : 0);
                uint32_t off = SWZ((uint32_t)(n * 128 + kk * 32 + ((lane >> 3) & 1) * 16));
                ldsm4(st + ST_BHI + off, bh[g]);
                ldsm4(st + ST_BLO + off, bl[g]);
            }
#pragma unroll
            for (int mi = 0; mi < 4; mi++)
#pragma unroll
                for (int nt = 0; nt < 4; nt++) {
                    const uint32_t* h2 = &bh[nt >> 1][(nt & 1) * 2];
                    const uint32_t* l2 = &bl[nt >> 1][(nt & 1) * 2];
                    mma16816(acc[mi][nt], ah[mi], h2);
                    mma16816(acc[mi][nt], ah[mi], l2);
                    mma16816(acc[mi][nt], al[mi], h2);
                }
        }
    }
}

// ---------------- fused QKV GEMM: C[M,1536] = A[M,512] @ Wqkv^T ----------------
// n-tile 0-3 -> q (relu), 4-7 -> k (+pos, relu), 8-11 -> v (plain)
__global__ __launch_bounds__(256, 1)
void gemm_qkv(const __nv_bfloat16* __restrict__ Ahi, const __nv_bfloat16* __restrict__ Alo,
              const __nv_bfloat16* __restrict__ Bhi, const __nv_bfloat16* __restrict__ Blo,
              float* __restrict__ qout, float* __restrict__ kout, float* __restrict__ vout,
              const float* __restrict__ pos)
{
    extern __shared__ char smem[];
    const int tid = threadIdx.x;
    const int wid = tid >> 5, lane = tid & 31;
    const int wm = wid & 1, wn = wid >> 1;
    const int m0 = blockIdx.y * 128;
    const int n0 = blockIdx.x * 128;           // 0..1408
    const int mode = blockIdx.x >> 2;          // 0=q 1=k 2=v
    const int ncol0 = n0 - mode * 512;         // column in the 512-wide output

    float acc[4][4][4];
#pragma unroll
    for (int a = 0; a < 4; a++)
#pragma unroll
        for (int b = 0; b < 4; b++)
#pragma unroll
            for (int e = 0; e < 4; e++) acc[a][b][e] = 0.f;

    gemm_mainloop(smem, m0, n0, tid, wm, wn, lane, Ahi, Alo, Bhi, Blo, acc);

    float* C = (mode == 0) ? qout : (mode == 1) ? kout : vout;
#pragma unroll
    for (int mi = 0; mi < 4; mi++) {
#pragma unroll
        for (int nt = 0; nt < 4; nt++) {
            int r0 = m0 + wm * 64 + mi * 16 + (lane >> 2);
            int col = ncol0 + wn * 32 + nt * 8 + (lane & 3) * 2;
#pragma unroll
            for (int half = 0; half < 2; half++) {
                int r = r0 + half * 8;
                float v0 = acc[mi][nt][half * 2 + 0];
                float v1 = acc[mi][nt][half * 2 + 1];
                if (mode == 1) {
                    const float2 pe = *(const float2*)(pos + (size_t)(r % NN) * DD + col);
                    v0 += pe.x; v1 += pe.y;
                }
                if (mode != 2) { v0 = fmaxf(v0, 0.f); v1 = fmaxf(v1, 0.f); }
                *(float2*)(C + (size_t)r * DD + col) = make_float2(v0, v1);
            }
        }
    }
}

// ---------------- final GEMM: out = y @ Wp + bp ----------------
__global__ __launch_bounds__(256, 1)
void gemm_out(const __nv_bfloat16* __restrict__ Ahi, const __nv_bfloat16* __restrict__ Alo,
              const __nv_bfloat16* __restrict__ Bhi, const __nv_bfloat16* __restrict__ Blo,
              float* __restrict__ C, const float* __restrict__ bias)
{
    extern __shared__ char smem[];
    const int tid = threadIdx.x;
    const int wid = tid >> 5, lane = tid & 31;
    const int wm = wid & 1, wn = wid >> 1;
    const int m0 = blockIdx.y * 128;
    const int n0 = blockIdx.x * 128;

    float acc[4][4][4];
#pragma unroll
    for (int a = 0; a < 4; a++)
#pragma unroll
        for (int b = 0; b < 4; b++)
#pragma unroll
            for (int e = 0; e < 4; e++) acc[a][b][e] = 0.f;

    gemm_mainloop(smem, m0, n0, tid, wm, wn, lane, Ahi, Alo, Bhi, Blo, acc);

#pragma unroll
    for (int mi = 0; mi < 4; mi++) {
#pragma unroll
        for (int nt = 0; nt < 4; nt++) {
            int r0 = m0 + wm * 64 + mi * 16 + (lane >> 2);
            int col = n0 + wn * 32 + nt * 8 + (lane & 3) * 2;
            const float2 bb = *(const float2*)(bias + col);
#pragma unroll
            for (int half = 0; half < 2; half++) {
                int r = r0 + half * 8;
                *(float2*)(C + (size_t)r * DD + col) =
                    make_float2(acc[mi][nt][half * 2 + 0] + bb.x,
                                acc[mi][nt][half * 2 + 1] + bb.y);
            }
        }
    }
}

// ---------------- ctx[d][e] = sum_n k[n,d]*v[n,e] per (b,h), split-K ----------------
__global__ __launch_bounds__(256)
void ctx_kernel()
{
    const int bh = blockIdx.x;
    const int s  = blockIdx.y;
    const int b = bh >> 3, h = bh & 7;
    __shared__ float4 ks4[16][16];
    __shared__ float4 vs4[16][16];

    const int tid = threadIdx.x;
    const int tx = tid & 15, ty = tid >> 4;
    const int lr = tid >> 4, lc = tid & 15;

    const float* kbase = g_k + (size_t)(b * NN) * DD + h * HDim;
    const float* vbase = g_v + (size_t)(b * NN) * DD + h * HDim;

    float acc[4][4] = {};
    float ks_acc[4] = {0.f, 0.f, 0.f, 0.f};
    const int n0 = s * TOKS;

    for (int t0 = 0; t0 < TOKS; t0 += 16) {
        ks4[lr][lc] = *(const float4*)(kbase + (size_t)(n0 + t0 + lr) * DD + lc * 4);
        vs4[lr][lc] = *(const float4*)(vbase + (size_t)(n0 + t0 + lr) * DD + lc * 4);
        __syncthreads();
#pragma unroll
        for (int kk = 0; kk < 16; kk++) {
            float4 a = ks4[kk][ty];
            float4 bv = vs4[kk][tx];
            acc[0][0] = fmaf(a.x, bv.x, acc[0][0]); acc[0][1] = fmaf(a.x, bv.y, acc[0][1]);
            acc[0][2] = fmaf(a.x, bv.z, acc[0][2]); acc[0][3] = fmaf(a.x, bv.w, acc[0][3]);
            acc[1][0] = fmaf(a.y, bv.x, acc[1][0]); acc[1][1] = fmaf(a.y, bv.y, acc[1][1]);
            acc[1][2] = fmaf(a.y, bv.z, acc[1][2]); acc[1][3] = fmaf(a.y, bv.w, acc[1][3]);
            acc[2][0] = fmaf(a.z, bv.x, acc[2][0]); acc[2][1] = fmaf(a.z, bv.y, acc[2][1]);
            acc[2][2] = fmaf(a.z, bv.z, acc[2][2]); acc[2][3] = fmaf(a.z, bv.w, acc[2][3]);
            acc[3][0] = fmaf(a.w, bv.x, acc[3][0]); acc[3][1] = fmaf(a.w, bv.y, acc[3][1]);
            acc[3][2] = fmaf(a.w, bv.z, acc[3][2]); acc[3][3] = fmaf(a.w, bv.w, acc[3][3]);
            if (tx == 0) {
                ks_acc[0] += a.x; ks_acc[1] += a.y; ks_acc[2] += a.z; ks_acc[3] += a.w;
            }
        }
        __syncthreads();
    }

    float* cp = g_ctx_part + ((size_t)s * 128 + bh) * 4096;
#pragma unroll
    for (int i = 0; i < 4; i++)
        *(float4*)&cp[(ty * 4 + i) * 64 + tx * 4] =
            make_float4(acc[i][0], acc[i][1], acc[i][2], acc[i][3]);
    if (tx == 0) {
        float* kp = g_ksum_part + ((size_t)s * 128 + bh) * 64;
#pragma unroll
        for (int i = 0; i < 4; i++) kp[ty * 4 + i] = ks_acc[i];
    }
}

__global__ void reduce_kernel()
{
    const int idx = blockIdx.x * 256 + threadIdx.x;
    if (idx < 128 * 4096) {
        float s = 0.f;
#pragma unroll
        for (int p = 0; p < SPLIT; p++) s += g_ctx_part[(size_t)p * 128 * 4096 + idx];
        g_ctx[idx] = s;
    } else {
        const int i2 = idx - 128 * 4096;
        if (i2 < 128 * 64) {
            float s = 0.f;
#pragma unroll
            for (int p = 0; p < SPLIT; p++) s += g_ksum_part[(size_t)p * 128 * 64 + i2];
            g_ksum[i2] = s;
        }
    }
}

// ---------------- attn ----------------
__global__ __launch_bounds__(256)
void attn_kernel()
{
    const int bh = blockIdx.y;
    const int b = bh >> 3, h = bh & 7;
    const int n0 = blockIdx.x * 64;
    __shared__ float  qs[64][65];
    __shared__ float4 ctxs4[64][16];
    __shared__ float  ksum_s[64];
    __shared__ float  dinv_s[64];

    const int tid = threadIdx.x;

    const float4* cg = (const float4*)(g_ctx + (size_t)bh * 4096);
#pragma unroll
    for (int i = 0; i < 4; i++) {
        int f = tid + i * 256;
        ((float4*)ctxs4)[f] = cg[f];
    }
    if (tid < 64) ksum_s[tid] = g_ksum[bh * 64 + tid];

    const float* qbase = g_q + (size_t)(b * NN) * DD + h * HDim;
#pragma unroll
    for (int i = 0; i < 4; i++) {
        int f = tid + i * 256;
        int r = f >> 4, c4 = f & 15;
        float4 v4 = *(const float4*)(qbase + (size_t)(n0 + r) * DD + c4 * 4);
        qs[r][c4 * 4 + 0] = v4.x; qs[r][c4 * 4 + 1] = v4.y;
        qs[r][c4 * 4 + 2] = v4.z; qs[r][c4 * 4 + 3] = v4.w;
    }
    __syncthreads();

    if (tid < 64) {
        float s = 0.f;
#pragma unroll
        for (int kk = 0; kk < 64; kk++) s = fmaf(qs[tid][kk], ksum_s[kk], s);
        dinv_s[tid] = 1.0f / (s + 1e-6f);
    }
    __syncthreads();

    const int tx = tid & 15, ty = tid >> 4;
    float acc[4][4] = {};
#pragma unroll
    for (int kk = 0; kk < 64; kk++) {
        float a0 = qs[ty * 4 + 0][kk];
        float a1 = qs[ty * 4 + 1][kk];
        float a2 = qs[ty * 4 + 2][kk];
        float a3 = qs[ty * 4 + 3][kk];
        float4 c = ctxs4[kk][tx];
        acc[0][0] = fmaf(a0, c.x, acc[0][0]); acc[0][1] = fmaf(a0, c.y, acc[0][1]);
        acc[0][2] = fmaf(a0, c.z, acc[0][2]); acc[0][3] = fmaf(a0, c.w, acc[0][3]);
        acc[1][0] = fmaf(a1, c.x, acc[1][0]); acc[1][1] = fmaf(a1, c.y, acc[1][1]);
        acc[1][2] = fmaf(a1, c.z, acc[1][2]); acc[1][3] = fmaf(a1, c.w, acc[1][3]);
        acc[2][0] = fmaf(a2, c.x, acc[2][0]); acc[2][1] = fmaf(a2, c.y, acc[2][1]);
        acc[2][2] = fmaf(a2, c.z, acc[2][2]); acc[2][3] = fmaf(a2, c.w, acc[2][3]);
        acc[3][0] = fmaf(a3, c.x, acc[3][0]); acc[3][1] = fmaf(a3, c.y, acc[3][1]);
        acc[3][2] = fmaf(a3, c.z, acc[3][2]); acc[3][3] = fmaf(a3, c.w, acc[3][3]);
    }

    float* ybase = g_y + ((size_t)bh * NN + n0) * HDim;
#pragma unroll
    for (int i = 0; i < 4; i++) {
        float di = dinv_s[ty * 4 + i];
        *(float4*)&ybase[(ty * 4 + i) * 64 + tx * 4] =
            make_float4(acc[i][0] * di, acc[i][1] * di, acc[i][2] * di, acc[i][3] * di);
    }
}

// ---------------- dwc: depthwise 5x5 + fused bf16 split of y ----------------
__global__ __launch_bounds__(256)
void dwc_kernel(const float* __restrict__ w, const float* __restrict__ bias)
{
    const int bh = blockIdx.y;
    const int b = bh >> 3, h = bh & 7;
    const int tid = threadIdx.x;

    __shared__ float ws[64 * 25];
    __shared__ float bs[64];
    for (int i = tid; i < 64 * 25; i += 256) ws[i] = w[i];
    if (tid < 64) bs[tid] = bias[tid];
    __syncthreads();

    const int c = tid & 63;
    const int p = blockIdx.x * 4 + (tid >> 6);
    const int pi = p / HH, pj = p % HH;

    const float* vbase = g_v + (size_t)(b * NN) * DD + h * HDim + c;
    float acc = 0.f;
#pragma unroll
    for (int di = 0; di < 5; di++) {
        const int ii = pi + di - 2;
        if ((unsigned)ii < (unsigned)HH) {
#pragma unroll
            for (int dj = 0; dj < 5; dj++) {
                const int jj = pj + dj - 2;
                if ((unsigned)jj < (unsigned)HH)
                    acc = fmaf(ws[c * 25 + di * 5 + dj],
                               vbase[(size_t)(ii * HH + jj) * DD], acc);
            }
        }
    }
    const size_t yi = ((size_t)bh * NN + p) * HDim + c;
    float total = g_y[yi] + acc + bs[c];
    __nv_bfloat16 hi = __float2bfloat16(total);
    g_yhi[yi] = hi;
    g_ylo[yi] = __float2bfloat16(total - __bfloat162float(hi));
}

// ---------------- launch ----------------
extern "C" void kernel_launch(void* const* d_in, const int* in_sizes, int n_in,
                              void* d_out, int out_size)
{
    const float* x    = (const float*)d_in[0];
    const float* Wq   = (const float*)d_in[1];
    const float* Wkv  = (const float*)d_in[2];
    const float* pos  = (const float*)d_in[3];
    const float* dwcw = (const float*)d_in[4];
    const float* dwcb = (const float*)d_in[5];
    const float* Wp   = (const float*)d_in[6];
    const float* bp   = (const float*)d_in[7];
    float* out = (float*)d_out;

    float *qptr, *kptr, *vptr;
    cudaGetSymbolAddress((void**)&qptr, g_q);
    cudaGetSymbolAddress((void**)&kptr, g_k);
    cudaGetSymbolAddress((void**)&vptr, g_v);
    __nv_bfloat16 *xhip, *xlop, *yhip, *ylop, *whip, *wlop;
    cudaGetSymbolAddress((void**)&xhip, g_xhi);
    cudaGetSymbolAddress((void**)&xlop, g_xlo);
    cudaGetSymbolAddress((void**)&yhip, g_yhi);
    cudaGetSymbolAddress((void**)&ylop, g_ylo);
    cudaGetSymbolAddress((void**)&whip, g_whi);
    cudaGetSymbolAddress((void**)&wlop, g_wlo);

    cudaFuncSetAttribute(gemm_qkv, cudaFuncAttributeMaxDynamicSharedMemorySize, GEMM_SMEM);
    cudaFuncSetAttribute(gemm_out, cudaFuncAttributeMaxDynamicSharedMemorySize, GEMM_SMEM);

    split_x_kernel<<<(MM * DD / 4) / 256, 256>>>(x);
    prep_w_kernel<<<(DD * DD) / 256, 256>>>(Wq, Wkv, Wp);

    const size_t WSZ = (size_t)DD * DD;
    gemm_qkv<<<dim3(12, MM / 128), 256, GEMM_SMEM>>>(
        xhip, xlop, whip, wlop, qptr, kptr, vptr, pos);

    ctx_kernel<<<dim3(128, SPLIT), 256>>>();
    reduce_kernel<<<(128 * 4096 + 128 * 64) / 256, 256>>>();
    attn_kernel<<<dim3(NN / 64, 128), 256>>>();
    dwc_kernel<<<dim3(NN / 4, 128), 256>>>(dwcw, dwcb);

    gemm_out<<<dim3(4, MM / 128), 256, GEMM_SMEM>>>(
        yhip, ylop, whip + 3 * WSZ, wlop + 3 * WSZ, out, bp);
}

// round 9
// speedup vs baseline: 1.0269x; 1.0269x over previous
#include <cuda_runtime.h>
#include <cuda_bf16.h>
#include <cstdint>

// ---------------- problem constants ----------------
#define BB   16
#define NN   3136
#define DD   512
#define HDim 64
#define MM   (BB * NN)        // 50176 rows
#define HH   56
#define SPLIT 14
#define TOKS  (NN / SPLIT)    // 224  (= 7 chunks of 32 tokens)

// ---------------- scratch ----------------
__device__ __align__(256) float g_q[(size_t)MM * DD];
__device__ __align__(256) float g_k[(size_t)MM * DD];
__device__ __align__(256) float g_v[(size_t)MM * DD];
__device__ __align__(256) float g_y[(size_t)MM * DD];
__device__ __align__(256) float g_ctx_part[(size_t)SPLIT * 128 * 64 * 64];
__device__ __align__(256) float g_ksum_part[(size_t)SPLIT * 128 * 64];
__device__ __align__(256) float g_ctx[(size_t)128 * 64 * 64];
__device__ __align__(256) float g_ksum[(size_t)128 * 64];

__device__ __align__(256) __nv_bfloat16 g_xhi[(size_t)MM * DD];
__device__ __align__(256) __nv_bfloat16 g_xlo[(size_t)MM * DD];
__device__ __align__(256) __nv_bfloat16 g_yhi[(size_t)MM * DD];
__device__ __align__(256) __nv_bfloat16 g_ylo[(size_t)MM * DD];
// transposed weights [n][k]: 0=Wq, 1=Wkv(k), 2=Wkv(v), 3=Wp
__device__ __align__(256) __nv_bfloat16 g_whi[4][(size_t)DD * DD];
__device__ __align__(256) __nv_bfloat16 g_wlo[4][(size_t)DD * DD];

// ---------------- helpers ----------------
__device__ __forceinline__ uint32_t smem_to_u32(const void* p) {
    uint32_t a;
    asm("{ .reg .u64 t; cvta.to.shared.u64 t, %1; cvt.u32.u64 %0, t; }" : "=r"(a) : "l"(p));
    return a;
}
#define SWZ(o) ((o) ^ (((o) >> 3) & 0x70))

#define CP16(dst, src) \
    asm volatile("cp.async.cg.shared.global [%0], [%1], 16;" :: "r"(dst), "l"(src) : "memory")
#define CP_COMMIT() asm volatile("cp.async.commit_group;" ::: "memory")
#define CP_WAIT(n)  asm volatile("cp.async.wait_group %0;" :: "n"(n) : "memory")

__device__ __forceinline__ void ldsm4(uint32_t addr, uint32_t* r) {
    asm volatile("ldmatrix.sync.aligned.m8n8.x4.shared.b16 {%0,%1,%2,%3}, [%4];"
                 : "=r"(r[0]), "=r"(r[1]), "=r"(r[2]), "=r"(r[3]) : "r"(addr));
}
__device__ __forceinline__ void mma16816(float* d, const uint32_t* a, const uint32_t* b) {
    asm volatile(
        "mma.sync.aligned.m16n8k16.row.col.f32.bf16.bf16.f32 "
        "{%0,%1,%2,%3}, {%4,%5,%6,%7}, {%8,%9}, {%0,%1,%2,%3};"
        : "+f"(d[0]), "+f"(d[1]), "+f"(d[2]), "+f"(d[3])
        : "r"(a[0]), "r"(a[1]), "r"(a[2]), "r"(a[3]), "r"(b[0]), "r"(b[1]));
}

// ---------------- input split kernels ----------------
__global__ __launch_bounds__(256)
void split_x_kernel(const float* __restrict__ x)
{
    size_t i = (size_t)blockIdx.x * 256 + threadIdx.x;   // over MM*DD/4
    float4 v = ((const float4*)x)[i];
    __nv_bfloat16 h0 = __float2bfloat16(v.x), h1 = __float2bfloat16(v.y);
    __nv_bfloat16 h2 = __float2bfloat16(v.z), h3 = __float2bfloat16(v.w);
    __nv_bfloat16 l0 = __float2bfloat16(v.x - __bfloat162float(h0));
    __nv_bfloat16 l1 = __float2bfloat16(v.y - __bfloat162float(h1));
    __nv_bfloat16 l2 = __float2bfloat16(v.z - __bfloat162float(h2));
    __nv_bfloat16 l3 = __float2bfloat16(v.w - __bfloat162float(h3));
    __nv_bfloat162* ph = (__nv_bfloat162*)g_xhi;
    __nv_bfloat162* pl = (__nv_bfloat162*)g_xlo;
    ph[2 * i + 0] = __nv_bfloat162(h0, h1);
    ph[2 * i + 1] = __nv_bfloat162(h2, h3);
    pl[2 * i + 0] = __nv_bfloat162(l0, l1);
    pl[2 * i + 1] = __nv_bfloat162(l2, l3);
}

__global__ __launch_bounds__(256)
void prep_w_kernel(const float* __restrict__ Wq, const float* __restrict__ Wkv,
                   const float* __restrict__ Wp)
{
    int idx = blockIdx.x * 256 + threadIdx.x;   // output [n][k]
    int n = idx / DD, k = idx % DD;
    float v0 = Wq[(size_t)k * DD + n];
    float v1 = Wkv[(size_t)k * 2 * DD + n];
    float v2 = Wkv[(size_t)k * 2 * DD + DD + n];
    float v3 = Wp[(size_t)k * DD + n];
#pragma unroll
    for (int m = 0; m < 4; m++) {
        float v = (m == 0) ? v0 : (m == 1) ? v1 : (m == 2) ? v2 : v3;
        __nv_bfloat16 h = __float2bfloat16(v);
        g_whi[m][idx] = h;
        g_wlo[m][idx] = __float2bfloat16(v - __bfloat162float(h));
    }
}

// ---------------- HMMA GEMM core: 512 threads, 16 warps (4m x 4n), warp tile 32x32 ----------------
#define ST_AHI 0
#define ST_ALO 16384
#define ST_BHI 32768
#define ST_BLO 49152
#define STAGE_BYTES 65536
#define GEMM_SMEM (2 * STAGE_BYTES)
#define GT 512

__device__ __forceinline__ void gemm_load_chunk(
    char* smem, int stage, int c, int m0, int n0, int tid,
    const __nv_bfloat16* __restrict__ Ahi, const __nv_bfloat16* __restrict__ Alo,
    const __nv_bfloat16* __restrict__ Bhi, const __nv_bfloat16* __restrict__ Blo)
{
    const uint32_t sb = smem_to_u32(smem) + stage * STAGE_BYTES;
#pragma unroll
    for (int i = 0; i < 2; i++) {
        int u = tid + i * GT;           // 0..1023 16B units
        int row = u >> 3, col = u & 7;
        uint32_t off = SWZ((uint32_t)(row * 128 + col * 16));
        size_t ga = (size_t)(m0 + row) * DD + c * 64 + col * 8;
        size_t gb = (size_t)(n0 + row) * DD + c * 64 + col * 8;
        CP16(sb + ST_AHI + off, Ahi + ga);
        CP16(sb + ST_ALO + off, Alo + ga);
        CP16(sb + ST_BHI + off, Bhi + gb);
        CP16(sb + ST_BLO + off, Blo + gb);
    }
}

__device__ __forceinline__ void gemm_mainloop(
    char* smem, int m0, int n0, int tid, int wm, int wn, int lane,
    const __nv_bfloat16* Ahi, const __nv_bfloat16* Alo,
    const __nv_bfloat16* Bhi, const __nv_bfloat16* Blo,
    float acc[2][4][4])
{
    gemm_load_chunk(smem, 0, 0, m0, n0, tid, Ahi, Alo, Bhi, Blo);
    CP_COMMIT();
    const uint32_t sbase = smem_to_u32(smem);

    for (int c = 0; c < 8; c++) {
        CP_WAIT(0);
        __syncthreads();
        if (c < 7) {
            gemm_load_chunk(smem, (c + 1) & 1, c + 1, m0, n0, tid, Ahi, Alo, Bhi, Blo);
            CP_COMMIT();
        }
        const uint32_t st = sbase + (c & 1) * STAGE_BYTES;
#pragma unroll
        for (int kk = 0; kk < 4; kk++) {
            uint32_t ah[2][4], al[2][4], bh[2][4], bl[2][4];
#pragma unroll
            for (int mi = 0; mi < 2; mi++) {
                int row = wm * 32 + mi * 16 + (lane & 15);
                uint32_t off = SWZ((uint32_t)(row * 128 + kk * 32 + (lane >> 4) * 16));
                ldsm4(st + ST_AHI + off, ah[mi]);
                ldsm4(st + ST_ALO + off, al[mi]);
            }
#pragma unroll
            for (int g = 0; g < 2; g++) {
                int n = wn * 32 + g * 16 + (lane & 7) + ((lane & 16) ? 8 : 0);
                uint32_t off = SWZ((uint32_t)(n * 128 + kk * 32 + ((lane >> 3) & 1) * 16));
                ldsm4(st + ST_BHI + off, bh[g]);
                ldsm4(st + ST_BLO + off, bl[g]);
            }
#pragma unroll
            for (int mi = 0; mi < 2; mi++)
#pragma unroll
                for (int nt = 0; nt < 4; nt++) {
                    const uint32_t* h2 = &bh[nt >> 1][(nt & 1) * 2];
                    const uint32_t* l2 = &bl[nt >> 1][(nt & 1) * 2];
                    mma16816(acc[mi][nt], ah[mi], h2);
                    mma16816(acc[mi][nt], ah[mi], l2);
                    mma16816(acc[mi][nt], al[mi], h2);
                }
        }
    }
}

// ---------------- fused QKV GEMM ----------------
__global__ __launch_bounds__(GT, 1)
void gemm_qkv(const __nv_bfloat16* __restrict__ Ahi, const __nv_bfloat16* __restrict__ Alo,
              const __nv_bfloat16* __restrict__ Bhi, const __nv_bfloat16* __restrict__ Blo,
              float* __restrict__ qout, float* __restrict__ kout, float* __restrict__ vout,
              const float* __restrict__ pos)
{
    extern __shared__ char smem[];
    const int tid = threadIdx.x;
    const int wid = tid >> 5, lane = tid & 31;
    const int wm = wid & 3, wn = wid >> 2;
    const int m0 = blockIdx.y * 128;
    const int n0 = blockIdx.x * 128;
    const int mode = blockIdx.x >> 2;          // 0=q 1=k 2=v
    const int ncol0 = n0 - mode * 512;

    float acc[2][4][4] = {};
    gemm_mainloop(smem, m0, n0, tid, wm, wn, lane, Ahi, Alo, Bhi, Blo, acc);

    float* C = (mode == 0) ? qout : (mode == 1) ? kout : vout;
#pragma unroll
    for (int mi = 0; mi < 2; mi++) {
#pragma unroll
        for (int nt = 0; nt < 4; nt++) {
            int r0 = m0 + wm * 32 + mi * 16 + (lane >> 2);
            int col = ncol0 + wn * 32 + nt * 8 + (lane & 3) * 2;
#pragma unroll
            for (int half = 0; half < 2; half++) {
                int r = r0 + half * 8;
                float v0 = acc[mi][nt][half * 2 + 0];
                float v1 = acc[mi][nt][half * 2 + 1];
                if (mode == 1) {
                    const float2 pe = *(const float2*)(pos + (size_t)(r % NN) * DD + col);
                    v0 += pe.x; v1 += pe.y;
                }
                if (mode != 2) { v0 = fmaxf(v0, 0.f); v1 = fmaxf(v1, 0.f); }
                *(float2*)(C + (size_t)r * DD + col) = make_float2(v0, v1);
            }
        }
    }
}

// ---------------- final GEMM: out = y @ Wp + bp ----------------
__global__ __launch_bounds__(GT, 1)
void gemm_out(const __nv_bfloat16* __restrict__ Ahi, const __nv_bfloat16* __restrict__ Alo,
              const __nv_bfloat16* __restrict__ Bhi, const __nv_bfloat16* __restrict__ Blo,
              float* __restrict__ C, const float* __restrict__ bias)
{
    extern __shared__ char smem[];
    const int tid = threadIdx.x;
    const int wid = tid >> 5, lane = tid & 31;
    const int wm = wid & 3, wn = wid >> 2;
    const int m0 = blockIdx.y * 128;
    const int n0 = blockIdx.x * 128;

    float acc[2][4][4] = {};
    gemm_mainloop(smem, m0, n0, tid, wm, wn, lane, Ahi, Alo, Bhi, Blo, acc);

#pragma unroll
    for (int mi = 0; mi < 2; mi++) {
#pragma unroll
        for (int nt = 0; nt < 4; nt++) {
            int r0 = m0 + wm * 32 + mi * 16 + (lane >> 2);
            int col = n0 + wn * 32 + nt * 8 + (lane & 3) * 2;
            const float2 bb = *(const float2*)(bias + col);
#pragma unroll
            for (int half = 0; half < 2; half++) {
                int r = r0 + half * 8;
                *(float2*)(C + (size_t)r * DD + col) =
                    make_float2(acc[mi][nt][half * 2 + 0] + bb.x,
                                acc[mi][nt][half * 2 + 1] + bb.y);
            }
        }
    }
}

// ---------------- ctx via HMMA: ctx[d][e] = sum_n k[n,d] v[n,e]  (+ ksum) ----------------
// 128 threads, 4 warps (2m x 2n), warp tile 32x32. Chunks of 32 tokens, double-buffered.
// smem layout per stage: 4 arrays (khi,klo,vhi,vlo), each [64 dims][stride 80B] (32 tokens x bf16)
#define CROW 80
#define CARR (64 * CROW)   // 5120

__global__ __launch_bounds__(128)
void ctx_mma_kernel()
{
    __shared__ __align__(16) char cbuf[2][4][CARR];
    __shared__ float ksred[128];

    const int bh = blockIdx.x;          // 0..127
    const int s  = blockIdx.y;          // 0..SPLIT-1
    const int b = bh >> 3, h = bh & 7;
    const int tid = threadIdx.x;
    const int lane = tid & 31, wid = tid >> 5;
    const int wm = wid & 1, wn = wid >> 1;
    const int dth = tid & 63;           // fixed dim per thread (conversion)
    const int nb  = tid >> 6;           // 0/1

    const float* kb = g_k + ((size_t)(b * NN) + (size_t)s * TOKS) * DD + h * HDim;
    const float* vb = g_v + ((size_t)(b * NN) + (size_t)s * TOKS) * DD + h * HDim;

    float kreg[16], vreg[16];
    float ksum_loc = 0.f;
    float acc[2][4][4] = {};

#pragma unroll
    for (int i = 0; i < 16; i++) {
        int n = nb + 2 * i;
        kreg[i] = kb[(size_t)n * DD + dth];
        vreg[i] = vb[(size_t)n * DD + dth];
    }

    for (int c = 0; c < 7; c++) {
        const int st = c & 1;
        char* k_hi = cbuf[st][0];
        char* k_lo = cbuf[st][1];
        char* v_hi = cbuf[st][2];
        char* v_lo = cbuf[st][3];
#pragma unroll
        for (int i = 0; i < 16; i++) {
            int n = nb + 2 * i;
            uint32_t off = (uint32_t)dth * CROW + n * 2;
            float kv = kreg[i], vv = vreg[i];
            ksum_loc += kv;
            __nv_bfloat16 kh = __float2bfloat16(kv);
            __nv_bfloat16 kl = __float2bfloat16(kv - __bfloat162float(kh));
            __nv_bfloat16 vh = __float2bfloat16(vv);
            __nv_bfloat16 vl = __float2bfloat16(vv - __bfloat162float(vh));
            *(__nv_bfloat16*)(k_hi + off) = kh;
            *(__nv_bfloat16*)(k_lo + off) = kl;
            *(__nv_bfloat16*)(v_hi + off) = vh;
            *(__nv_bfloat16*)(v_lo + off) = vl;
        }
        if (c < 6) {
            const float* kb2 = kb + (size_t)(c + 1) * 32 * DD;
            const float* vb2 = vb + (size_t)(c + 1) * 32 * DD;
#pragma unroll
            for (int i = 0; i < 16; i++) {
                int n = nb + 2 * i;
                kreg[i] = kb2[(size_t)n * DD + dth];
                vreg[i] = vb2[(size_t)n * DD + dth];
            }
        }
        __syncthreads();

        const uint32_t base = smem_to_u32(cbuf[st][0]);
#pragma unroll
        for (int kk = 0; kk < 2; kk++) {
            uint32_t ah[2][4], al[2][4], bh2[2][4], bl2[2][4];
#pragma unroll
            for (int mi = 0; mi < 2; mi++) {
                int row = wm * 32 + mi * 16 + (lane & 15);
                uint32_t off = (uint32_t)row * CROW + kk * 32 + (lane >> 4) * 16;
                ldsm4(base + 0 * CARR + off, ah[mi]);
                ldsm4(base + 1 * CARR + off, al[mi]);
            }
#pragma unroll
            for (int g = 0; g < 2; g++) {
                int e = wn * 32 + g * 16 + (lane & 7) + ((lane & 16) ? 8 : 0);
                uint32_t off = (uint32_t)e * CROW + kk * 32 + ((lane >> 3) & 1) * 16;
                ldsm4(base + 2 * CARR + off, bh2[g]);
                ldsm4(base + 3 * CARR + off, bl2[g]);
            }
#pragma unroll
            for (int mi = 0; mi < 2; mi++)
#pragma unroll
                for (int nt = 0; nt < 4; nt++) {
                    const uint32_t* h2 = &bh2[nt >> 1][(nt & 1) * 2];
                    const uint32_t* l2 = &bl2[nt >> 1][(nt & 1) * 2];
                    mma16816(acc[mi][nt], ah[mi], h2);
                    mma16816(acc[mi][nt], ah[mi], l2);
                    mma16816(acc[mi][nt], al[mi], h2);
                }
        }
    }

    // write ctx partials
    float* cp = g_ctx_part + ((size_t)s * 128 + bh) * 4096;
#pragma unroll
    for (int mi = 0; mi < 2; mi++)
#pragma unroll
        for (int nt = 0; nt < 4; nt++) {
            int r = wm * 32 + mi * 16 + (lane >> 2);
            int col = wn * 32 + nt * 8 + (lane & 3) * 2;
            *(float2*)&cp[r * 64 + col] = make_float2(acc[mi][nt][0], acc[mi][nt][1]);
            *(float2*)&cp[(r + 8) * 64 + col] = make_float2(acc[mi][nt][2], acc[mi][nt][3]);
        }

    // ksum partials
    ksred[tid] = ksum_loc;
    __syncthreads();
    if (tid < 64)
        g_ksum_part[((size_t)s * 128 + bh) * 64 + tid] = ksred[tid] + ksred[tid + 64];
}

__global__ void reduce_kernel()
{
    const int idx = blockIdx.x * 256 + threadIdx.x;
    if (idx < 128 * 4096) {
        float s = 0.f;
#pragma unroll
        for (int p = 0; p < SPLIT; p++) s += g_ctx_part[(size_t)p * 128 * 4096 + idx];
        g_ctx[idx] = s;
    } else {
        const int i2 = idx - 128 * 4096;
        if (i2 < 128 * 64) {
            float s = 0.f;
#pragma unroll
            for (int p = 0; p < SPLIT; p++) s += g_ksum_part[(size_t)p * 128 * 64 + i2];
            g_ksum[i2] = s;
        }
    }
}

// ---------------- attn ----------------
__global__ __launch_bounds__(256)
void attn_kernel()
{
    const int bh = blockIdx.y;
    const int b = bh >> 3, h = bh & 7;
    const int n0 = blockIdx.x * 64;
    __shared__ float  qs[64][65];
    __shared__ float4 ctxs4[64][16];
    __shared__ float  ksum_s[64];
    __shared__ float  dinv_s[64];

    const int tid = threadIdx.x;

    const float4* cg = (const float4*)(g_ctx + (size_t)bh * 4096);
#pragma unroll
    for (int i = 0; i < 4; i++) {
        int f = tid + i * 256;
        ((float4*)ctxs4)[f] = cg[f];
    }
    if (tid < 64) ksum_s[tid] = g_ksum[bh * 64 + tid];

    const float* qbase = g_q + (size_t)(b * NN) * DD + h * HDim;
#pragma unroll
    for (int i = 0; i < 4; i++) {
        int f = tid + i * 256;
        int r = f >> 4, c4 = f & 15;
        float4 v4 = *(const float4*)(qbase + (size_t)(n0 + r) * DD + c4 * 4);
        qs[r][c4 * 4 + 0] = v4.x; qs[r][c4 * 4 + 1] = v4.y;
        qs[r][c4 * 4 + 2] = v4.z; qs[r][c4 * 4 + 3] = v4.w;
    }
    __syncthreads();

    if (tid < 64) {
        float s = 0.f;
#pragma unroll
        for (int kk = 0; kk < 64; kk++) s = fmaf(qs[tid][kk], ksum_s[kk], s);
        dinv_s[tid] = 1.0f / (s + 1e-6f);
    }
    __syncthreads();

    const int tx = tid & 15, ty = tid >> 4;
    float acc[4][4] = {};
#pragma unroll
    for (int kk = 0; kk < 64; kk++) {
        float a0 = qs[ty * 4 + 0][kk];
        float a1 = qs[ty * 4 + 1][kk];
        float a2 = qs[ty * 4 + 2][kk];
        float a3 = qs[ty * 4 + 3][kk];
        float4 c = ctxs4[kk][tx];
        acc[0][0] = fmaf(a0, c.x, acc[0][0]); acc[0][1] = fmaf(a0, c.y, acc[0][1]);
        acc[0][2] = fmaf(a0, c.z, acc[0][2]); acc[0][3] = fmaf(a0, c.w, acc[0][3]);
        acc[1][0] = fmaf(a1, c.x, acc[1][0]); acc[1][1] = fmaf(a1, c.y, acc[1][1]);
        acc[1][2] = fmaf(a1, c.z, acc[1][2]); acc[1][3] = fmaf(a1, c.w, acc[1][3]);
        acc[2][0] = fmaf(a2, c.x, acc[2][0]); acc[2][1] = fmaf(a2, c.y, acc[2][1]);
        acc[2][2] = fmaf(a2, c.z, acc[2][2]); acc[2][3] = fmaf(a2, c.w, acc[2][3]);
        acc[3][0] = fmaf(a3, c.x, acc[3][0]); acc[3][1] = fmaf(a3, c.y, acc[3][1]);
        acc[3][2] = fmaf(a3, c.z, acc[3][2]); acc[3][3] = fmaf(a3, c.w, acc[3][3]);
    }

    float* ybase = g_y + ((size_t)bh * NN + n0) * HDim;
#pragma unroll
    for (int i = 0; i < 4; i++) {
        float di = dinv_s[ty * 4 + i];
        *(float4*)&ybase[(ty * 4 + i) * 64 + tx * 4] =
            make_float4(acc[i][0] * di, acc[i][1] * di, acc[i][2] * di, acc[i][3] * di);
    }
}

// ---------------- dwc: depthwise 5x5 + fused bf16 split of y ----------------
__global__ __launch_bounds__(256)
void dwc_kernel(const float* __restrict__ w, const float* __restrict__ bias)
{
    const int bh = blockIdx.y;
    const int b = bh >> 3, h = bh & 7;
    const int tid = threadIdx.x;

    __shared__ float ws[64 * 25];
    __shared__ float bs[64];
    for (int i = tid; i < 64 * 25; i += 256) ws[i] = w[i];
    if (tid < 64) bs[tid] = bias[tid];
    __syncthreads();

    const int c = tid & 63;
    const int p = blockIdx.x * 4 + (tid >> 6);
    const int pi = p / HH, pj = p % HH;

    const float* vbase = g_v + (size_t)(b * NN) * DD + h * HDim + c;
    float acc = 0.f;
#pragma unroll
    for (int di = 0; di < 5; di++) {
        const int ii = pi + di - 2;
        if ((unsigned)ii < (unsigned)HH) {
#pragma unroll
            for (int dj = 0; dj < 5; dj++) {
                const int jj = pj + dj - 2;
                if ((unsigned)jj < (unsigned)HH)
                    acc = fmaf(ws[c * 25 + di * 5 + dj],
                               vbase[(size_t)(ii * HH + jj) * DD], acc);
            }
        }
    }
    const size_t yi = ((size_t)bh * NN + p) * HDim + c;
    float total = g_y[yi] + acc + bs[c];
    __nv_bfloat16 hi = __float2bfloat16(total);
    g_yhi[yi] = hi;
    g_ylo[yi] = __float2bfloat16(total - __bfloat162float(hi));
}

// ---------------- launch ----------------
extern "C" void kernel_launch(void* const* d_in, const int* in_sizes, int n_in,
                              void* d_out, int out_size)
{
    const float* x    = (const float*)d_in[0];
    const float* Wq   = (const float*)d_in[1];
    const float* Wkv  = (const float*)d_in[2];
    const float* pos  = (const float*)d_in[3];
    const float* dwcw = (const float*)d_in[4];
    const float* dwcb = (const float*)d_in[5];
    const float* Wp   = (const float*)d_in[6];
    const float* bp   = (const float*)d_in[7];
    float* out = (float*)d_out;

    float *qptr, *kptr, *vptr;
    cudaGetSymbolAddress((void**)&qptr, g_q);
    cudaGetSymbolAddress((void**)&kptr, g_k);
    cudaGetSymbolAddress((void**)&vptr, g_v);
    __nv_bfloat16 *xhip, *xlop, *yhip, *ylop, *whip, *wlop;
    cudaGetSymbolAddress((void**)&xhip, g_xhi);
    cudaGetSymbolAddress((void**)&xlop, g_xlo);
    cudaGetSymbolAddress((void**)&yhip, g_yhi);
    cudaGetSymbolAddress((void**)&ylop, g_ylo);
    cudaGetSymbolAddress((void**)&whip, g_whi);
    cudaGetSymbolAddress((void**)&wlop, g_wlo);

    cudaFuncSetAttribute(gemm_qkv, cudaFuncAttributeMaxDynamicSharedMemorySize, GEMM_SMEM);
    cudaFuncSetAttribute(gemm_out, cudaFuncAttributeMaxDynamicSharedMemorySize, GEMM_SMEM);

    split_x_kernel<<<(MM * DD / 4) / 256, 256>>>(x);
    prep_w_kernel<<<(DD * DD) / 256, 256>>>(Wq, Wkv, Wp);

    const size_t WSZ = (size_t)DD * DD;
    gemm_qkv<<<dim3(12, MM / 128), GT, GEMM_SMEM>>>(
        xhip, xlop, whip, wlop, qptr, kptr, vptr, pos);

    ctx_mma_kernel<<<dim3(128, SPLIT), 128>>>();
    reduce_kernel<<<(128 * 4096 + 128 * 64) / 256, 256>>>();
    attn_kernel<<<dim3(NN / 64, 128), 256>>>();
    dwc_kernel<<<dim3(NN / 4, 128), 256>>>(dwcw, dwcb);

    gemm_out<<<dim3(4, MM / 128), GT, GEMM_SMEM>>>(
        yhip, ylop, whip + 3 * WSZ, wlop + 3 * WSZ, out, bp);
}